// round 13
// baseline (speedup 1.0000x reference)
#include <cuda_runtime.h>
#include <math.h>

#define NPTS 16384
#define DIM  64
#define NC   9
#define CAP  16384   // per-class region capacity
#define IT   64      // i-tile (= block size: 1 thread per i-row)
#define JT   16      // j-tile rows staged in smem
#define RATIO 4      // IT/JT
#define NB3  888     // KB grid (6 per SM, one wave)
#define KAB  128     // KA blocks

typedef unsigned long long u64;

// packed f32x2 fma: acc = a*b + acc (elementwise on 2 packed floats)
#define FMA2(acc, a, b) \
    asm("fma.rn.f32x2 %0, %1, %2, %3;" : "=l"(acc) : "l"(a), "l"(b), "l"(acc))

__device__ __forceinline__ float sum2(u64 v) {
    float2 f = *(float2*)&v;
    return f.x + f.y;
}

// ---- device scratch ----
__device__ float g_cf[8 * CAP * DIM];    // class-region normalized feats
__device__ int   g_fill[NC] = {0, 0, CAP, 2*CAP, 3*CAP, 4*CAP, 5*CAP, 6*CAP, 7*CAP};
__device__ float g_sum[NC * DIM];        // per-class normalized-feature sums
__device__ float g_cross[NC * NC];       // UNORDERED relu(dot) sums per class pair
__device__ unsigned g_t3;

// ---- KA: classify + normalize + scatter, fully thread-per-point ----
__global__ void __launch_bounds__(128) ka_classify_scatter(
        const int* __restrict__ labels,
        const float* __restrict__ feats,
        const float* __restrict__ scores) {
    int tid = threadIdx.x;
    int p = blockIdx.x * 128 + tid;

    const float* sr = scores + p * NC;
    float sv[NC];
    #pragma unroll
    for (int c = 0; c < NC; c++) sv[c] = __ldg(&sr[c]);
    float mv = sv[0]; int mi = 0;
    #pragma unroll
    for (int c = 1; c < NC; c++) if (sv[c] > mv) { mv = sv[c]; mi = c; }
    float e = 0.f;
    #pragma unroll
    for (int c = 0; c < NC; c++) e += expf(sv[c] - mv);
    float pmax = 1.0f / e;

    int lab = labels[p];
    int cls = (lab == mi && pmax >= 0.5f && lab >= 1) ? lab : 0;
    if (cls == 0) return;

    // private row load: 16 independent LDG.128 (MLP-covered)
    const float4* fr = (const float4*)(feats + p * DIM);
    float4 v[16];
    #pragma unroll
    for (int q = 0; q < 16; q++) v[q] = __ldg(&fr[q]);
    float ss = 0.f;
    #pragma unroll
    for (int q = 0; q < 16; q++)
        ss += v[q].x * v[q].x + v[q].y * v[q].y + v[q].z * v[q].z + v[q].w * v[q].w;
    float inv = 1.0f / fmaxf(sqrtf(ss), 1e-12f);

    int slot = atomicAdd(&g_fill[cls], 1);
    float4* dst = (float4*)(g_cf + slot * DIM);
    float* sum = g_sum + cls * DIM;
    #pragma unroll
    for (int q = 0; q < 16; q++) {
        float4 w = make_float4(v[q].x * inv, v[q].y * inv, v[q].z * inv, v[q].w * inv);
        dst[q] = w;
        atomicAdd(&sum[q * 4 + 0], w.x);
        atomicAdd(&sum[q * 4 + 1], w.y);
        atomicAdd(&sum[q * 4 + 2], w.z);
        atomicAdd(&sum[q * 4 + 3], w.w);
    }
}

// ---- KB: triangular pairwise relu(dot); 8 short FMA2 chains per j-pair ----
__global__ void __launch_bounds__(64, 6) kb_pairs(float* __restrict__ out) {
    __shared__ ulonglong2 Js[JT][17];   // pitch 17: conflict-free, 16B aligned
    __shared__ float  scross[NC * NC];
    __shared__ int    s_pre[NC + 1];
    __shared__ int    s_base[NC];
    __shared__ int    jphys[JT];

    int tid = threadIdx.x;
    for (int i = tid; i < NC * NC; i += 64) scross[i] = 0.f;
    if (tid == 0) {
        int acc = 0;
        #pragma unroll
        for (int c = 1; c < NC; c++) {
            int base = (c - 1) * CAP;
            s_base[c] = base;
            s_pre[c] = acc;
            acc += g_fill[c] - base;
        }
        s_pre[NC] = acc;
    }
    __syncthreads();

    int nv = s_pre[NC];
    int nit = (nv + IT - 1) / IT;
    int njt = (nv + JT - 1) / JT;
    // job (it, jt) needed iff jt >= RATIO*it
    int njobs = nit * njt - RATIO * nit * (nit - 1) / 2;

    const ulonglong2* cfp = (const ulonglong2*)g_cf;   // 16 per row

    for (int job = blockIdx.x; job < njobs; job += NB3) {
        int it = 0, rem = job;
        while (rem >= njt - RATIO * it) { rem -= njt - RATIO * it; it++; }
        int jt = RATIO * it + rem;
        int jb = jt * JT;

        int iv = it * IT + tid;
        int ci = 0, iphys = 0;
        {
            int c = 1;
            #pragma unroll
            for (int cc = 2; cc < NC; cc++) if (iv >= s_pre[cc]) c = cc;
            iphys = s_base[c] + (iv - s_pre[c]);
            ci = (iv < nv) ? c : 0;
        }
        // i-row in registers as 32 packed f32x2
        u64 rowp[32];
        #pragma unroll
        for (int c4 = 0; c4 < 16; c4++) {
            ulonglong2 t = cfp[iphys * 16 + c4];
            rowp[2 * c4]     = t.x;
            rowp[2 * c4 + 1] = t.y;
        }

        int jmin = iv - jb;   // valid pairs need local j > jmin

        __syncthreads();
        if (tid < JT) {
            int jv = jb + tid;
            int c = 1;
            #pragma unroll
            for (int cc = 2; cc < NC; cc++) if (jv >= s_pre[cc]) c = cc;
            jphys[tid] = (jv < nv) ? (s_base[c] + (jv - s_pre[c])) : 0;
        }
        __syncthreads();
        #pragma unroll
        for (int q0 = 0; q0 < JT * 16; q0 += 64) {
            int q = q0 + tid;
            Js[q >> 4][q & 15] = cfp[jphys[q >> 4] * 16 + (q & 15)];
        }
        __syncthreads();

        if (ci > 0) {
            #pragma unroll
            for (int c = 1; c < NC; c++) {
                if (c == ci) continue;
                int rs = max(s_pre[c] - jb, 0);
                int re = min(s_pre[c + 1] - jb, JT);
                int j = max(rs, jmin + 1);      // skip sub-diagonal j entirely
                if (j >= re) continue;
                float rsum = 0.f;
                for (; j + 1 < re; j += 2) {
                    u64 a0 = 0ull, a1 = 0ull, a2 = 0ull, a3 = 0ull;
                    u64 b0 = 0ull, b1 = 0ull, b2 = 0ull, b3 = 0ull;
                    #pragma unroll
                    for (int c4 = 0; c4 < 8; c4++) {
                        ulonglong2 p0 = Js[j][c4];
                        ulonglong2 p1 = Js[j][c4 + 8];
                        ulonglong2 q0 = Js[j + 1][c4];
                        ulonglong2 q1 = Js[j + 1][c4 + 8];
                        FMA2(a0, rowp[2 * c4],            p0.x);
                        FMA2(a1, rowp[2 * c4 + 1],        p0.y);
                        FMA2(a2, rowp[2 * (c4 + 8)],      p1.x);
                        FMA2(a3, rowp[2 * (c4 + 8) + 1],  p1.y);
                        FMA2(b0, rowp[2 * c4],            q0.x);
                        FMA2(b1, rowp[2 * c4 + 1],        q0.y);
                        FMA2(b2, rowp[2 * (c4 + 8)],      q1.x);
                        FMA2(b3, rowp[2 * (c4 + 8) + 1],  q1.y);
                    }
                    float s0 = fmaxf((sum2(a0) + sum2(a1)) + (sum2(a2) + sum2(a3)), 0.f);
                    float s1 = fmaxf((sum2(b0) + sum2(b1)) + (sum2(b2) + sum2(b3)), 0.f);
                    rsum += s0 + s1;
                }
                if (j < re) {
                    u64 a0 = 0ull, a1 = 0ull, a2 = 0ull, a3 = 0ull;
                    #pragma unroll
                    for (int c4 = 0; c4 < 8; c4++) {
                        ulonglong2 p0 = Js[j][c4];
                        ulonglong2 p1 = Js[j][c4 + 8];
                        FMA2(a0, rowp[2 * c4],            p0.x);
                        FMA2(a1, rowp[2 * c4 + 1],        p0.y);
                        FMA2(a2, rowp[2 * (c4 + 8)],      p1.x);
                        FMA2(a3, rowp[2 * (c4 + 8) + 1],  p1.y);
                    }
                    rsum += fmaxf((sum2(a0) + sum2(a1)) + (sum2(a2) + sum2(a3)), 0.f);
                }
                if (rsum > 0.f) {
                    int lo = min(ci, c), hi = max(ci, c);
                    atomicAdd(&scross[lo * NC + hi], rsum);
                }
            }
        }
    }
    __syncthreads();
    for (int i = tid; i < NC * NC; i += 64)
        if (scross[i] != 0.f) atomicAdd(&g_cross[i], scross[i]);

    // ---- last-block finalize + reset for next graph replay ----
    __shared__ bool is_last;
    __threadfence();
    __syncthreads();
    if (tid == 0) is_last = (atomicAdd(&g_t3, 1u) == NB3 - 1);
    __syncthreads();
    if (!is_last) return;
    __threadfence();

    __shared__ float red[64];
    float acc = 0.f;
    if (tid >= 1 && tid < NC) {
        float cnt = (float)(s_pre[tid + 1] - s_pre[tid]);
        float quad = 0.f;
        #pragma unroll
        for (int d = 0; d < DIM; d++) {
            float vv = g_sum[tid * DIM + d];
            quad += vv * vv;
        }
        float npairs = cnt * (cnt - 1.0f) * 0.5f;
        if (npairs > 0.f)
            acc += 1.0f - ((quad - cnt) * 0.5f) / npairs;
    }
    for (int idx = tid; idx < NC * NC; idx += 64) {
        int a = idx / NC, b = idx % NC;
        if (a >= 1 && b > a) {
            float ca = (float)(s_pre[a + 1] - s_pre[a]);
            float cb = (float)(s_pre[b + 1] - s_pre[b]);
            float den = ca * cb;
            if (den > 0.f) acc += g_cross[a * NC + b] / den;
        }
    }
    red[tid] = acc;
    __syncthreads();
    #pragma unroll
    for (int o = 32; o > 0; o >>= 1) {
        if (tid < o) red[tid] += red[tid + o];
        __syncthreads();
    }
    if (tid == 0) out[0] = red[0];

    // reset for next replay
    __syncthreads();
    if (tid >= 1 && tid < NC) g_fill[tid] = (tid - 1) * CAP;
    for (int i = tid; i < NC * NC; i += 64) g_cross[i] = 0.f;
    for (int i = tid; i < NC * DIM; i += 64) g_sum[i] = 0.f;
    if (tid == 0) g_t3 = 0;
}

extern "C" void kernel_launch(void* const* d_in, const int* in_sizes, int n_in,
                              void* d_out, int out_size) {
    const int*   labels = nullptr;
    const float* feats  = nullptr;
    const float* scores = nullptr;
    for (int i = 0; i < n_in; i++) {
        if (in_sizes[i] == NPTS)            labels = (const int*)d_in[i];
        else if (in_sizes[i] == NPTS * DIM) feats  = (const float*)d_in[i];
        else if (in_sizes[i] == NPTS * NC)  scores = (const float*)d_in[i];
    }
    float* out = (float*)d_out;

    ka_classify_scatter<<<KAB, 128>>>(labels, feats, scores);
    kb_pairs<<<NB3, 64>>>(out);
}

// round 14
// speedup vs baseline: 1.2955x; 1.2955x over previous
#include <cuda_runtime.h>
#include <math.h>

#define NPTS 16384
#define DIM  64
#define NC   9
#define CAP  16384   // per-class region capacity
#define IT   64      // i-tile (= block size: 1 thread per i-row)
#define JT   16      // j-tile rows staged in smem
#define RATIO 4      // IT/JT
#define NB3  1184    // KB grid (8 per SM, one wave)
#define KAB  128     // KA blocks

typedef unsigned long long u64;

// packed f32x2 fma: acc = a*b + acc (elementwise on 2 packed floats)
#define FMA2(acc, a, b) \
    asm("fma.rn.f32x2 %0, %1, %2, %3;" : "=l"(acc) : "l"(a), "l"(b), "l"(acc))

__device__ __forceinline__ float sum2(u64 v) {
    float2 f = *(float2*)&v;
    return f.x + f.y;
}

// ---- device scratch ----
__device__ float g_cf[8 * CAP * DIM];    // class-region normalized feats
__device__ int   g_fill[NC] = {0, 0, CAP, 2*CAP, 3*CAP, 4*CAP, 5*CAP, 6*CAP, 7*CAP};
__device__ float g_sum[NC * DIM];        // per-class normalized-feature sums
__device__ float g_cross[NC * NC];       // UNORDERED relu(dot) sums per class pair
__device__ unsigned g_t3;

// ---- KA: fused classify + normalize + warp-cooperative scatter (R11 form) ----
__global__ void __launch_bounds__(128) ka_classify_scatter(
        const int* __restrict__ labels,
        const float* __restrict__ feats,
        const float* __restrict__ scores) {
    int tid = threadIdx.x;
    int lane = tid & 31;
    int p = blockIdx.x * 128 + tid;

    const float* sr = scores + p * NC;
    float sv[NC];
    #pragma unroll
    for (int c = 0; c < NC; c++) sv[c] = __ldg(&sr[c]);
    float mv = sv[0]; int mi = 0;
    #pragma unroll
    for (int c = 1; c < NC; c++) if (sv[c] > mv) { mv = sv[c]; mi = c; }
    float e = 0.f;
    #pragma unroll
    for (int c = 0; c < NC; c++) e += expf(sv[c] - mv);
    float pmax = 1.0f / e;

    int lab = labels[p];
    int cls = (lab == mi && pmax >= 0.5f && lab >= 1) ? lab : 0;

    unsigned bal = __ballot_sync(0xffffffffu, cls > 0);
    while (bal) {
        int src = __ffs(bal) - 1;
        bal &= bal - 1;
        int pc = __shfl_sync(0xffffffffu, cls, src);
        int pp = __shfl_sync(0xffffffffu, p, src);

        float x0 = feats[pp * DIM + lane];
        float x1 = feats[pp * DIM + 32 + lane];
        float ss = x0 * x0 + x1 * x1;
        #pragma unroll
        for (int o = 16; o > 0; o >>= 1) ss += __shfl_xor_sync(0xffffffffu, ss, o);
        float inv = 1.0f / fmaxf(sqrtf(ss), 1e-12f);
        float f0 = x0 * inv, f1 = x1 * inv;

        int slot;
        if (lane == 0) slot = atomicAdd(&g_fill[pc], 1);
        slot = __shfl_sync(0xffffffffu, slot, 0);

        g_cf[slot * DIM + lane]      = f0;
        g_cf[slot * DIM + 32 + lane] = f1;
        atomicAdd(&g_sum[pc * DIM + lane],      f0);
        atomicAdd(&g_sum[pc * DIM + 32 + lane], f1);
    }
}

// ---- KB: triangular pairwise relu(dot); 8 FMA2 chains, 8 blocks/SM ----
__global__ void __launch_bounds__(64, 8) kb_pairs(float* __restrict__ out) {
    __shared__ ulonglong2 Js[JT][17];   // pitch 17: conflict-free, 16B aligned
    __shared__ float  scross[NC * NC];
    __shared__ int    s_pre[NC + 1];
    __shared__ int    s_base[NC];
    __shared__ int    jphys[JT];

    int tid = threadIdx.x;
    for (int i = tid; i < NC * NC; i += 64) scross[i] = 0.f;
    if (tid == 0) {
        int acc = 0;
        #pragma unroll
        for (int c = 1; c < NC; c++) {
            int base = (c - 1) * CAP;
            s_base[c] = base;
            s_pre[c] = acc;
            acc += g_fill[c] - base;
        }
        s_pre[NC] = acc;
    }
    __syncthreads();

    int nv = s_pre[NC];
    int nit = (nv + IT - 1) / IT;
    int njt = (nv + JT - 1) / JT;
    // job (it, jt) needed iff jt >= RATIO*it
    int njobs = nit * njt - RATIO * nit * (nit - 1) / 2;

    const ulonglong2* cfp = (const ulonglong2*)g_cf;   // 16 per row

    for (int job = blockIdx.x; job < njobs; job += NB3) {
        int it = 0, rem = job;
        while (rem >= njt - RATIO * it) { rem -= njt - RATIO * it; it++; }
        int jt = RATIO * it + rem;
        int jb = jt * JT;

        int iv = it * IT + tid;
        int ci = 0, iphys = 0;
        {
            int c = 1;
            #pragma unroll
            for (int cc = 2; cc < NC; cc++) if (iv >= s_pre[cc]) c = cc;
            iphys = s_base[c] + (iv - s_pre[c]);
            ci = (iv < nv) ? c : 0;
        }
        // i-row in registers as 32 packed f32x2
        u64 rowp[32];
        #pragma unroll
        for (int c4 = 0; c4 < 16; c4++) {
            ulonglong2 t = cfp[iphys * 16 + c4];
            rowp[2 * c4]     = t.x;
            rowp[2 * c4 + 1] = t.y;
        }

        int jmin = iv - jb;   // valid pairs need local j > jmin

        __syncthreads();
        if (tid < JT) {
            int jv = jb + tid;
            int c = 1;
            #pragma unroll
            for (int cc = 2; cc < NC; cc++) if (jv >= s_pre[cc]) c = cc;
            jphys[tid] = (jv < nv) ? (s_base[c] + (jv - s_pre[c])) : 0;
        }
        __syncthreads();
        #pragma unroll
        for (int q0 = 0; q0 < JT * 16; q0 += 64) {
            int q = q0 + tid;
            Js[q >> 4][q & 15] = cfp[jphys[q >> 4] * 16 + (q & 15)];
        }
        __syncthreads();

        if (ci > 0) {
            #pragma unroll
            for (int c = 1; c < NC; c++) {
                if (c == ci) continue;
                int rs = max(s_pre[c] - jb, 0);
                int re = min(s_pre[c + 1] - jb, JT);
                int j = max(rs, jmin + 1);      // skip sub-diagonal j entirely
                if (j >= re) continue;
                float rsum = 0.f;
                for (; j + 1 < re; j += 2) {
                    u64 a0 = 0ull, a1 = 0ull, a2 = 0ull, a3 = 0ull;
                    u64 b0 = 0ull, b1 = 0ull, b2 = 0ull, b3 = 0ull;
                    #pragma unroll
                    for (int c4 = 0; c4 < 8; c4++) {
                        ulonglong2 p0 = Js[j][c4];
                        ulonglong2 p1 = Js[j][c4 + 8];
                        ulonglong2 q0 = Js[j + 1][c4];
                        ulonglong2 q1 = Js[j + 1][c4 + 8];
                        FMA2(a0, rowp[2 * c4],            p0.x);
                        FMA2(a1, rowp[2 * c4 + 1],        p0.y);
                        FMA2(a2, rowp[2 * (c4 + 8)],      p1.x);
                        FMA2(a3, rowp[2 * (c4 + 8) + 1],  p1.y);
                        FMA2(b0, rowp[2 * c4],            q0.x);
                        FMA2(b1, rowp[2 * c4 + 1],        q0.y);
                        FMA2(b2, rowp[2 * (c4 + 8)],      q1.x);
                        FMA2(b3, rowp[2 * (c4 + 8) + 1],  q1.y);
                    }
                    float s0 = fmaxf((sum2(a0) + sum2(a1)) + (sum2(a2) + sum2(a3)), 0.f);
                    float s1 = fmaxf((sum2(b0) + sum2(b1)) + (sum2(b2) + sum2(b3)), 0.f);
                    rsum += s0 + s1;
                }
                if (j < re) {
                    u64 a0 = 0ull, a1 = 0ull, a2 = 0ull, a3 = 0ull;
                    #pragma unroll
                    for (int c4 = 0; c4 < 8; c4++) {
                        ulonglong2 p0 = Js[j][c4];
                        ulonglong2 p1 = Js[j][c4 + 8];
                        FMA2(a0, rowp[2 * c4],            p0.x);
                        FMA2(a1, rowp[2 * c4 + 1],        p0.y);
                        FMA2(a2, rowp[2 * (c4 + 8)],      p1.x);
                        FMA2(a3, rowp[2 * (c4 + 8) + 1],  p1.y);
                    }
                    rsum += fmaxf((sum2(a0) + sum2(a1)) + (sum2(a2) + sum2(a3)), 0.f);
                }
                if (rsum > 0.f) {
                    int lo = min(ci, c), hi = max(ci, c);
                    atomicAdd(&scross[lo * NC + hi], rsum);
                }
            }
        }
    }
    __syncthreads();
    for (int i = tid; i < NC * NC; i += 64)
        if (scross[i] != 0.f) atomicAdd(&g_cross[i], scross[i]);

    // ---- last-block finalize + reset for next graph replay ----
    __shared__ bool is_last;
    __threadfence();
    __syncthreads();
    if (tid == 0) is_last = (atomicAdd(&g_t3, 1u) == NB3 - 1);
    __syncthreads();
    if (!is_last) return;
    __threadfence();

    __shared__ float red[64];
    float acc = 0.f;
    if (tid >= 1 && tid < NC) {
        float cnt = (float)(s_pre[tid + 1] - s_pre[tid]);
        float quad = 0.f;
        #pragma unroll
        for (int d = 0; d < DIM; d++) {
            float vv = g_sum[tid * DIM + d];
            quad += vv * vv;
        }
        float npairs = cnt * (cnt - 1.0f) * 0.5f;
        if (npairs > 0.f)
            acc += 1.0f - ((quad - cnt) * 0.5f) / npairs;
    }
    for (int idx = tid; idx < NC * NC; idx += 64) {
        int a = idx / NC, b = idx % NC;
        if (a >= 1 && b > a) {
            float ca = (float)(s_pre[a + 1] - s_pre[a]);
            float cb = (float)(s_pre[b + 1] - s_pre[b]);
            float den = ca * cb;
            if (den > 0.f) acc += g_cross[a * NC + b] / den;
        }
    }
    red[tid] = acc;
    __syncthreads();
    #pragma unroll
    for (int o = 32; o > 0; o >>= 1) {
        if (tid < o) red[tid] += red[tid + o];
        __syncthreads();
    }
    if (tid == 0) out[0] = red[0];

    // reset for next replay
    __syncthreads();
    if (tid >= 1 && tid < NC) g_fill[tid] = (tid - 1) * CAP;
    for (int i = tid; i < NC * NC; i += 64) g_cross[i] = 0.f;
    for (int i = tid; i < NC * DIM; i += 64) g_sum[i] = 0.f;
    if (tid == 0) g_t3 = 0;
}

extern "C" void kernel_launch(void* const* d_in, const int* in_sizes, int n_in,
                              void* d_out, int out_size) {
    const int*   labels = nullptr;
    const float* feats  = nullptr;
    const float* scores = nullptr;
    for (int i = 0; i < n_in; i++) {
        if (in_sizes[i] == NPTS)            labels = (const int*)d_in[i];
        else if (in_sizes[i] == NPTS * DIM) feats  = (const float*)d_in[i];
        else if (in_sizes[i] == NPTS * NC)  scores = (const float*)d_in[i];
    }
    float* out = (float*)d_out;

    ka_classify_scatter<<<KAB, 128>>>(labels, feats, scores);
    kb_pairs<<<NB3, 64>>>(out);
}

// round 15
// speedup vs baseline: 1.2969x; 1.0010x over previous
#include <cuda_runtime.h>
#include <math.h>

#define NPTS 16384
#define DIM  64
#define NC   9
#define CAP  16384   // per-class region capacity
#define IT   64      // i-tile (= block size: 1 thread per i-row)
#define JT   16      // j-tile rows staged in smem
#define RATIO 4      // IT/JT
#define NB3  1184    // KB grid (8 per SM, one wave)
#define KAB  128     // KA blocks

typedef unsigned long long u64;

// packed f32x2 fma: acc = a*b + acc (elementwise on 2 packed floats)
#define FMA2(acc, a, b) \
    asm("fma.rn.f32x2 %0, %1, %2, %3;" : "=l"(acc) : "l"(a), "l"(b), "l"(acc))

__device__ __forceinline__ float sum2(u64 v) {
    float2 f = *(float2*)&v;
    return f.x + f.y;
}

// ---- device scratch ----
__device__ float g_cf[8 * CAP * DIM];    // class-region normalized feats
__device__ int   g_fill[NC] = {0, 0, CAP, 2*CAP, 3*CAP, 4*CAP, 5*CAP, 6*CAP, 7*CAP};
__device__ float g_sum[NC * DIM];        // per-class normalized-feature sums
__device__ float g_cross[NC * NC];       // UNORDERED relu(dot) sums per class pair

// ---- KA: fused classify + normalize + warp-cooperative scatter ----
__global__ void __launch_bounds__(128) ka_classify_scatter(
        const int* __restrict__ labels,
        const float* __restrict__ feats,
        const float* __restrict__ scores) {
    int tid = threadIdx.x;
    int lane = tid & 31;
    int p = blockIdx.x * 128 + tid;

    const float* sr = scores + p * NC;
    float sv[NC];
    #pragma unroll
    for (int c = 0; c < NC; c++) sv[c] = __ldg(&sr[c]);
    float mv = sv[0]; int mi = 0;
    #pragma unroll
    for (int c = 1; c < NC; c++) if (sv[c] > mv) { mv = sv[c]; mi = c; }
    float e = 0.f;
    #pragma unroll
    for (int c = 0; c < NC; c++) e += expf(sv[c] - mv);
    float pmax = 1.0f / e;

    int lab = labels[p];
    int cls = (lab == mi && pmax >= 0.5f && lab >= 1) ? lab : 0;

    unsigned bal = __ballot_sync(0xffffffffu, cls > 0);
    while (bal) {
        int src = __ffs(bal) - 1;
        bal &= bal - 1;
        int pc = __shfl_sync(0xffffffffu, cls, src);
        int pp = __shfl_sync(0xffffffffu, p, src);

        float x0 = feats[pp * DIM + lane];
        float x1 = feats[pp * DIM + 32 + lane];
        float ss = x0 * x0 + x1 * x1;
        #pragma unroll
        for (int o = 16; o > 0; o >>= 1) ss += __shfl_xor_sync(0xffffffffu, ss, o);
        float inv = 1.0f / fmaxf(sqrtf(ss), 1e-12f);
        float f0 = x0 * inv, f1 = x1 * inv;

        int slot;
        if (lane == 0) slot = atomicAdd(&g_fill[pc], 1);
        slot = __shfl_sync(0xffffffffu, slot, 0);

        g_cf[slot * DIM + lane]      = f0;
        g_cf[slot * DIM + 32 + lane] = f1;
        atomicAdd(&g_sum[pc * DIM + lane],      f0);
        atomicAdd(&g_sum[pc * DIM + 32 + lane], f1);
    }
}

// ---- KB: triangular pairwise relu(dot); no ticket, no finalize ----
__global__ void __launch_bounds__(64, 8) kb_pairs() {
    __shared__ ulonglong2 Js[JT][17];   // pitch 17: conflict-free, 16B aligned
    __shared__ float  scross[NC * NC];

    int tid = threadIdx.x;
    for (int i = tid; i < NC * NC; i += 64) scross[i] = 0.f;

    // per-thread register prefix (9 broadcast LDGs; no smem, no sync)
    int pre[NC + 1];
    pre[1] = 0;
    #pragma unroll
    for (int c = 1; c < NC; c++)
        pre[c + 1] = pre[c] + (__ldg(&g_fill[c]) - (c - 1) * CAP);
    int nv = pre[NC];

    int nit = (nv + IT - 1) / IT;
    int njt = (nv + JT - 1) / JT;
    int njobs = nit * njt - RATIO * nit * (nit - 1) / 2;

    const ulonglong2* cfp = (const ulonglong2*)g_cf;   // 16 per row

    for (int job = blockIdx.x; job < njobs; job += NB3) {
        int it = 0, rem = job;
        while (rem >= njt - RATIO * it) { rem -= njt - RATIO * it; it++; }
        int jt = RATIO * it + rem;
        int jb = jt * JT;

        int iv = it * IT + tid;
        int ci = 1, istart = 0;
        #pragma unroll
        for (int cc = 2; cc < NC; cc++)
            if (iv >= pre[cc]) { ci = cc; istart = pre[cc]; }
        int iphys = (ci - 1) * CAP + (iv - istart);
        if (iv >= nv) ci = 0;

        u64 rowp[32];
        #pragma unroll
        for (int c4 = 0; c4 < 16; c4++) {
            ulonglong2 t = cfp[iphys * 16 + c4];
            rowp[2 * c4]     = t.x;
            rowp[2 * c4 + 1] = t.y;
        }

        int jmin = iv - jb;   // valid pairs need local j > jmin

        __syncthreads();      // protect Js from previous job's readers
        #pragma unroll
        for (int q0 = 0; q0 < JT * 16; q0 += 64) {
            int q = q0 + tid;
            int r = q >> 4;
            int jv = jb + r;
            int jc = 1, jstart = 0;
            #pragma unroll
            for (int cc = 2; cc < NC; cc++)
                if (jv >= pre[cc]) { jc = cc; jstart = pre[cc]; }
            int jp = (jv < nv) ? ((jc - 1) * CAP + (jv - jstart)) : 0;
            Js[r][q & 15] = cfp[jp * 16 + (q & 15)];
        }
        __syncthreads();

        if (ci > 0) {
            #pragma unroll
            for (int c = 1; c < NC; c++) {
                if (c == ci) continue;
                int rs = max(pre[c] - jb, 0);
                int re = min(pre[c + 1] - jb, JT);
                int j = max(rs, jmin + 1);      // skip sub-diagonal j entirely
                if (j >= re) continue;
                float rsum = 0.f;
                for (; j + 1 < re; j += 2) {
                    u64 a0 = 0ull, a1 = 0ull, a2 = 0ull, a3 = 0ull;
                    u64 b0 = 0ull, b1 = 0ull, b2 = 0ull, b3 = 0ull;
                    #pragma unroll
                    for (int c4 = 0; c4 < 8; c4++) {
                        ulonglong2 p0 = Js[j][c4];
                        ulonglong2 p1 = Js[j][c4 + 8];
                        ulonglong2 q0 = Js[j + 1][c4];
                        ulonglong2 q1 = Js[j + 1][c4 + 8];
                        FMA2(a0, rowp[2 * c4],            p0.x);
                        FMA2(a1, rowp[2 * c4 + 1],        p0.y);
                        FMA2(a2, rowp[2 * (c4 + 8)],      p1.x);
                        FMA2(a3, rowp[2 * (c4 + 8) + 1],  p1.y);
                        FMA2(b0, rowp[2 * c4],            q0.x);
                        FMA2(b1, rowp[2 * c4 + 1],        q0.y);
                        FMA2(b2, rowp[2 * (c4 + 8)],      q1.x);
                        FMA2(b3, rowp[2 * (c4 + 8) + 1],  q1.y);
                    }
                    float s0 = fmaxf((sum2(a0) + sum2(a1)) + (sum2(a2) + sum2(a3)), 0.f);
                    float s1 = fmaxf((sum2(b0) + sum2(b1)) + (sum2(b2) + sum2(b3)), 0.f);
                    rsum += s0 + s1;
                }
                if (j < re) {
                    u64 a0 = 0ull, a1 = 0ull, a2 = 0ull, a3 = 0ull;
                    #pragma unroll
                    for (int c4 = 0; c4 < 8; c4++) {
                        ulonglong2 p0 = Js[j][c4];
                        ulonglong2 p1 = Js[j][c4 + 8];
                        FMA2(a0, rowp[2 * c4],            p0.x);
                        FMA2(a1, rowp[2 * c4 + 1],        p0.y);
                        FMA2(a2, rowp[2 * (c4 + 8)],      p1.x);
                        FMA2(a3, rowp[2 * (c4 + 8) + 1],  p1.y);
                    }
                    rsum += fmaxf((sum2(a0) + sum2(a1)) + (sum2(a2) + sum2(a3)), 0.f);
                }
                if (rsum > 0.f) {
                    int lo = min(ci, c), hi = max(ci, c);
                    atomicAdd(&scross[lo * NC + hi], rsum);
                }
            }
        }
    }
    __syncthreads();
    for (int i = tid; i < NC * NC; i += 64)
        if (scross[i] != 0.f) atomicAdd(&g_cross[i], scross[i]);
    // exit — no ticket, no fence; kernel boundary orders KC
}

// ---- KC: finalize + reset (single tiny block) ----
__global__ void __launch_bounds__(128) kc_final(float* __restrict__ out) {
    __shared__ float red[128];
    __shared__ int s_pre[NC + 1];
    int tid = threadIdx.x;

    if (tid == 0) {
        int acc = 0;
        #pragma unroll
        for (int c = 1; c < NC; c++) {
            s_pre[c] = acc;
            acc += g_fill[c] - (c - 1) * CAP;
        }
        s_pre[NC] = acc;
    }
    __syncthreads();

    float acc = 0.f;
    if (tid >= 1 && tid < NC) {
        float cnt = (float)(s_pre[tid + 1] - s_pre[tid]);
        float quad = 0.f;
        #pragma unroll
        for (int d = 0; d < DIM; d++) {
            float vv = g_sum[tid * DIM + d];
            quad += vv * vv;
        }
        float npairs = cnt * (cnt - 1.0f) * 0.5f;
        if (npairs > 0.f)
            acc += 1.0f - ((quad - cnt) * 0.5f) / npairs;
    }
    for (int idx = tid; idx < NC * NC; idx += 128) {
        int a = idx / NC, b = idx % NC;
        if (a >= 1 && b > a) {
            float ca = (float)(s_pre[a + 1] - s_pre[a]);
            float cb = (float)(s_pre[b + 1] - s_pre[b]);
            float den = ca * cb;
            if (den > 0.f) acc += g_cross[a * NC + b] / den;
        }
    }
    red[tid] = acc;
    __syncthreads();
    #pragma unroll
    for (int o = 64; o > 0; o >>= 1) {
        if (tid < o) red[tid] += red[tid + o];
        __syncthreads();
    }
    if (tid == 0) out[0] = red[0];

    // reset for next graph replay
    __syncthreads();
    if (tid >= 1 && tid < NC) g_fill[tid] = (tid - 1) * CAP;
    if (tid < NC * NC) g_cross[tid] = 0.f;
    for (int i = tid; i < NC * DIM; i += 128) g_sum[i] = 0.f;
}

extern "C" void kernel_launch(void* const* d_in, const int* in_sizes, int n_in,
                              void* d_out, int out_size) {
    const int*   labels = nullptr;
    const float* feats  = nullptr;
    const float* scores = nullptr;
    for (int i = 0; i < n_in; i++) {
        if (in_sizes[i] == NPTS)            labels = (const int*)d_in[i];
        else if (in_sizes[i] == NPTS * DIM) feats  = (const float*)d_in[i];
        else if (in_sizes[i] == NPTS * NC)  scores = (const float*)d_in[i];
    }
    float* out = (float*)d_out;

    ka_classify_scatter<<<KAB, 128>>>(labels, feats, scores);
    kb_pairs<<<NB3, 64>>>();
    kc_final<<<1, 128>>>(out);
}

// round 16
// speedup vs baseline: 1.6003x; 1.2339x over previous
#include <cuda_runtime.h>
#include <math.h>

#define NPTS 16384
#define DIM  64
#define NC   9
#define CAP  16384   // per-class region capacity
#define IT   64      // i-tile (= block size: 1 thread per i-row)
#define JT   16      // j-tile rows staged in smem
#define RATIO 4      // IT/JT
#define NB3  1184    // KB grid (8 per SM, one wave)
#define KAB  64      // KA blocks (64 x 256 = 16384 threads)

typedef unsigned long long u64;

// packed f32x2 fma: acc = a*b + acc (elementwise on 2 packed floats)
#define FMA2(acc, a, b) \
    asm("fma.rn.f32x2 %0, %1, %2, %3;" : "=l"(acc) : "l"(a), "l"(b), "l"(acc))

__device__ __forceinline__ float sum2(u64 v) {
    float2 f = *(float2*)&v;
    return f.x + f.y;
}

// ---- device scratch ----
__device__ float g_cf[8 * CAP * DIM];    // class-region normalized feats
__device__ int   g_fill[NC] = {0, 0, CAP, 2*CAP, 3*CAP, 4*CAP, 5*CAP, 6*CAP, 7*CAP};
__device__ float g_sum[NC * DIM];        // per-class normalized-feature sums
__device__ float g_cross[NC * NC];       // UNORDERED relu(dot) sums per class pair

// ---- KA: classify + block-batched slot alloc + pipelined scatter ----
__global__ void __launch_bounds__(256) ka_classify_scatter(
        const int* __restrict__ labels,
        const float* __restrict__ feats,
        const float* __restrict__ scores) {
    __shared__ int hist[NC];     // per-class count in block (doubles as rank src)
    __shared__ int cbase[NC];    // per-class base slot for this block
    __shared__ int s_n;          // dense list size
    __shared__ int s_p[256], s_c[256], s_slot[256];

    int tid = threadIdx.x;
    int lane = tid & 31, wid = tid >> 5;
    if (tid < NC) hist[tid] = 0;
    if (tid == 0) s_n = 0;
    __syncthreads();

    int p = blockIdx.x * 256 + tid;
    const float* sr = scores + p * NC;
    float sv[NC];
    #pragma unroll
    for (int c = 0; c < NC; c++) sv[c] = __ldg(&sr[c]);
    float mv = sv[0]; int mi = 0;
    #pragma unroll
    for (int c = 1; c < NC; c++) if (sv[c] > mv) { mv = sv[c]; mi = c; }
    float e = 0.f;
    #pragma unroll
    for (int c = 0; c < NC; c++) e += expf(sv[c] - mv);
    float pmax = 1.0f / e;

    int lab = labels[p];
    int cls = (lab == mi && pmax >= 0.5f && lab >= 1) ? lab : 0;

    int rank = 0;
    if (cls > 0) rank = atomicAdd(&hist[cls], 1);
    __syncthreads();
    if (tid >= 1 && tid < NC) {
        int h = hist[tid];
        if (h > 0) cbase[tid] = atomicAdd(&g_fill[tid], h);   // ONE atomic/class/block
    }
    __syncthreads();
    if (cls > 0) {
        int pos = atomicAdd(&s_n, 1);
        s_p[pos]    = p;
        s_c[pos]    = cls;
        s_slot[pos] = cbase[cls] + rank;
    }
    __syncthreads();

    // warp-strided, software-pipelined row processing
    int nvb = s_n;
    int idx = wid;
    int pp = 0, pc = 0, sl = 0;
    float x0 = 0.f, x1 = 0.f;
    if (idx < nvb) {
        pp = s_p[idx]; pc = s_c[idx]; sl = s_slot[idx];
        x0 = feats[pp * DIM + lane];
        x1 = feats[pp * DIM + 32 + lane];
    }
    while (idx < nvb) {
        int ni = idx + 8;
        int npp = 0, npc = 0, nsl = 0;
        float nx0 = 0.f, nx1 = 0.f;
        if (ni < nvb) {           // prefetch next item (overlaps processing below)
            npp = s_p[ni]; npc = s_c[ni]; nsl = s_slot[ni];
            nx0 = feats[npp * DIM + lane];
            nx1 = feats[npp * DIM + 32 + lane];
        }
        float ss = x0 * x0 + x1 * x1;
        #pragma unroll
        for (int o = 16; o > 0; o >>= 1) ss += __shfl_xor_sync(0xffffffffu, ss, o);
        float inv = 1.0f / fmaxf(sqrtf(ss), 1e-12f);
        float f0 = x0 * inv, f1 = x1 * inv;

        g_cf[sl * DIM + lane]      = f0;
        g_cf[sl * DIM + 32 + lane] = f1;
        atomicAdd(&g_sum[pc * DIM + lane],      f0);
        atomicAdd(&g_sum[pc * DIM + 32 + lane], f1);

        idx = ni; pp = npp; pc = npc; sl = nsl; x0 = nx0; x1 = nx1;
    }
}

// ---- KB: triangular pairwise relu(dot); no ticket, no finalize ----
__global__ void __launch_bounds__(64, 8) kb_pairs() {
    __shared__ ulonglong2 Js[JT][17];   // pitch 17: conflict-free, 16B aligned
    __shared__ float  scross[NC * NC];

    int tid = threadIdx.x;
    for (int i = tid; i < NC * NC; i += 64) scross[i] = 0.f;

    // per-thread register prefix (9 broadcast LDGs; no smem, no sync)
    int pre[NC + 1];
    pre[1] = 0;
    #pragma unroll
    for (int c = 1; c < NC; c++)
        pre[c + 1] = pre[c] + (__ldg(&g_fill[c]) - (c - 1) * CAP);
    int nv = pre[NC];

    int nit = (nv + IT - 1) / IT;
    int njt = (nv + JT - 1) / JT;
    int njobs = nit * njt - RATIO * nit * (nit - 1) / 2;

    const ulonglong2* cfp = (const ulonglong2*)g_cf;   // 16 per row

    for (int job = blockIdx.x; job < njobs; job += NB3) {
        int it = 0, rem = job;
        while (rem >= njt - RATIO * it) { rem -= njt - RATIO * it; it++; }
        int jt = RATIO * it + rem;
        int jb = jt * JT;

        int iv = it * IT + tid;
        int ci = 1, istart = 0;
        #pragma unroll
        for (int cc = 2; cc < NC; cc++)
            if (iv >= pre[cc]) { ci = cc; istart = pre[cc]; }
        int iphys = (ci - 1) * CAP + (iv - istart);
        if (iv >= nv) ci = 0;

        u64 rowp[32];
        #pragma unroll
        for (int c4 = 0; c4 < 16; c4++) {
            ulonglong2 t = cfp[iphys * 16 + c4];
            rowp[2 * c4]     = t.x;
            rowp[2 * c4 + 1] = t.y;
        }

        int jmin = iv - jb;   // valid pairs need local j > jmin

        __syncthreads();      // protect Js from previous job's readers
        #pragma unroll
        for (int q0 = 0; q0 < JT * 16; q0 += 64) {
            int q = q0 + tid;
            int r = q >> 4;
            int jv = jb + r;
            int jc = 1, jstart = 0;
            #pragma unroll
            for (int cc = 2; cc < NC; cc++)
                if (jv >= pre[cc]) { jc = cc; jstart = pre[cc]; }
            int jp = (jv < nv) ? ((jc - 1) * CAP + (jv - jstart)) : 0;
            Js[r][q & 15] = cfp[jp * 16 + (q & 15)];
        }
        __syncthreads();

        if (ci > 0) {
            #pragma unroll
            for (int c = 1; c < NC; c++) {
                if (c == ci) continue;
                int rs = max(pre[c] - jb, 0);
                int re = min(pre[c + 1] - jb, JT);
                int j = max(rs, jmin + 1);      // skip sub-diagonal j entirely
                if (j >= re) continue;
                float rsum = 0.f;
                for (; j + 1 < re; j += 2) {
                    u64 a0 = 0ull, a1 = 0ull, a2 = 0ull, a3 = 0ull;
                    u64 b0 = 0ull, b1 = 0ull, b2 = 0ull, b3 = 0ull;
                    #pragma unroll
                    for (int c4 = 0; c4 < 8; c4++) {
                        ulonglong2 p0 = Js[j][c4];
                        ulonglong2 p1 = Js[j][c4 + 8];
                        ulonglong2 q0 = Js[j + 1][c4];
                        ulonglong2 q1 = Js[j + 1][c4 + 8];
                        FMA2(a0, rowp[2 * c4],            p0.x);
                        FMA2(a1, rowp[2 * c4 + 1],        p0.y);
                        FMA2(a2, rowp[2 * (c4 + 8)],      p1.x);
                        FMA2(a3, rowp[2 * (c4 + 8) + 1],  p1.y);
                        FMA2(b0, rowp[2 * c4],            q0.x);
                        FMA2(b1, rowp[2 * c4 + 1],        q0.y);
                        FMA2(b2, rowp[2 * (c4 + 8)],      q1.x);
                        FMA2(b3, rowp[2 * (c4 + 8) + 1],  q1.y);
                    }
                    float s0 = fmaxf((sum2(a0) + sum2(a1)) + (sum2(a2) + sum2(a3)), 0.f);
                    float s1 = fmaxf((sum2(b0) + sum2(b1)) + (sum2(b2) + sum2(b3)), 0.f);
                    rsum += s0 + s1;
                }
                if (j < re) {
                    u64 a0 = 0ull, a1 = 0ull, a2 = 0ull, a3 = 0ull;
                    #pragma unroll
                    for (int c4 = 0; c4 < 8; c4++) {
                        ulonglong2 p0 = Js[j][c4];
                        ulonglong2 p1 = Js[j][c4 + 8];
                        FMA2(a0, rowp[2 * c4],            p0.x);
                        FMA2(a1, rowp[2 * c4 + 1],        p0.y);
                        FMA2(a2, rowp[2 * (c4 + 8)],      p1.x);
                        FMA2(a3, rowp[2 * (c4 + 8) + 1],  p1.y);
                    }
                    rsum += fmaxf((sum2(a0) + sum2(a1)) + (sum2(a2) + sum2(a3)), 0.f);
                }
                if (rsum > 0.f) {
                    int lo = min(ci, c), hi = max(ci, c);
                    atomicAdd(&scross[lo * NC + hi], rsum);
                }
            }
        }
    }
    __syncthreads();
    for (int i = tid; i < NC * NC; i += 64)
        if (scross[i] != 0.f) atomicAdd(&g_cross[i], scross[i]);
    // exit — kernel boundary orders KC
}

// ---- KC: finalize + reset (single tiny block) ----
__global__ void __launch_bounds__(128) kc_final(float* __restrict__ out) {
    __shared__ float red[128];
    __shared__ int s_pre[NC + 1];
    int tid = threadIdx.x;

    if (tid == 0) {
        int acc = 0;
        #pragma unroll
        for (int c = 1; c < NC; c++) {
            s_pre[c] = acc;
            acc += g_fill[c] - (c - 1) * CAP;
        }
        s_pre[NC] = acc;
    }
    __syncthreads();

    float acc = 0.f;
    if (tid >= 1 && tid < NC) {
        float cnt = (float)(s_pre[tid + 1] - s_pre[tid]);
        float quad = 0.f;
        #pragma unroll
        for (int d = 0; d < DIM; d++) {
            float vv = g_sum[tid * DIM + d];
            quad += vv * vv;
        }
        float npairs = cnt * (cnt - 1.0f) * 0.5f;
        if (npairs > 0.f)
            acc += 1.0f - ((quad - cnt) * 0.5f) / npairs;
    }
    for (int idx = tid; idx < NC * NC; idx += 128) {
        int a = idx / NC, b = idx % NC;
        if (a >= 1 && b > a) {
            float ca = (float)(s_pre[a + 1] - s_pre[a]);
            float cb = (float)(s_pre[b + 1] - s_pre[b]);
            float den = ca * cb;
            if (den > 0.f) acc += g_cross[a * NC + b] / den;
        }
    }
    red[tid] = acc;
    __syncthreads();
    #pragma unroll
    for (int o = 64; o > 0; o >>= 1) {
        if (tid < o) red[tid] += red[tid + o];
        __syncthreads();
    }
    if (tid == 0) out[0] = red[0];

    // reset for next graph replay
    __syncthreads();
    if (tid >= 1 && tid < NC) g_fill[tid] = (tid - 1) * CAP;
    if (tid < NC * NC) g_cross[tid] = 0.f;
    for (int i = tid; i < NC * DIM; i += 128) g_sum[i] = 0.f;
}

extern "C" void kernel_launch(void* const* d_in, const int* in_sizes, int n_in,
                              void* d_out, int out_size) {
    const int*   labels = nullptr;
    const float* feats  = nullptr;
    const float* scores = nullptr;
    for (int i = 0; i < n_in; i++) {
        if (in_sizes[i] == NPTS)            labels = (const int*)d_in[i];
        else if (in_sizes[i] == NPTS * DIM) feats  = (const float*)d_in[i];
        else if (in_sizes[i] == NPTS * NC)  scores = (const float*)d_in[i];
    }
    float* out = (float*)d_out;

    ka_classify_scatter<<<KAB, 256>>>(labels, feats, scores);
    kb_pairs<<<NB3, 64>>>();
    kc_final<<<1, 128>>>(out);
}